// round 13
// baseline (speedup 1.0000x reference)
#include <cuda_runtime.h>
#include <mma.h>
#include <math.h>

using namespace nvcuda;

#define T 2048
#define DIM 768
#define NH 12
#define HD 64
#define NCHUNK 4          // kt chunks per q-tile (8 kt-tiles = 512 keys each)
#define CHUNK_KT 8
#define QT 128            // attention q-tile rows

// Scratch (allocation-free: __device__ globals)
__device__ float g_qkv[3][T * DIM];        // raw q,k,v projections, [t][768]
__device__ float g_q[T * DIM];             // [h][t][64]
__device__ float g_k[T * DIM];             // [h][t][64]
__device__ float g_v[T * DIM];             // [h][t][64]
__device__ float g_att[T * DIM];           // attention output, [t][768]
__device__ float g_opart[NCHUNK][T * DIM]; // unnormalized partial O per chunk
__device__ float g_lpart[NCHUNK][NH * T];  // partial row sums per chunk

__device__ __forceinline__ float tf32c(float x) { return wmma::__float_to_tf32(x); }

// ---------------------------------------------------------------------------
// TF32 wmma GEMM-NT, BM=64 (2x the CTAs of the 128 version -> 3-4 CTAs/SM so
// barrier/mem latency overlaps across CTAs). Double-buffered BK=16, one
// __syncthreads per k-step. 8 warps (4m x 2n), warp tile 16x32.
// ---------------------------------------------------------------------------
#define BM 64
#define BN 64
#define BK 16

__device__ __forceinline__ void gemm_tile_tf32(const float* __restrict__ A,
                                               const float* __restrict__ B,
                                               float* __restrict__ C) {
    __shared__ float As[2][BM][BK];
    __shared__ float Bs[2][BN][BK];
    const int tid = threadIdx.x;
    const int wid = tid >> 5;
    const int m0 = blockIdx.y * BM, n0 = blockIdx.x * BN;
    const int warp_m = wid >> 1;   // 0..3 -> 16-row slice
    const int warp_n = wid & 1;    // 0..1 -> 32-col slice
    const int r = tid >> 2;        // 0..63
    const int c4 = (tid & 3) * 4;  // 0..12

    wmma::fragment<wmma::accumulator, 16, 16, 8, float> acc[2];
#pragma unroll
    for (int j = 0; j < 2; j++) wmma::fill_fragment(acc[j], 0.0f);

    float4 pa, pb;
    auto load_regs = [&](int k0) {
        pa = *(const float4*)&A[(m0 + r) * DIM + k0 + c4];
        pb = *(const float4*)&B[(n0 + r) * DIM + k0 + c4];
    };
    auto store_smem = [&](int buf) {
        As[buf][r][c4 + 0] = tf32c(pa.x); As[buf][r][c4 + 1] = tf32c(pa.y);
        As[buf][r][c4 + 2] = tf32c(pa.z); As[buf][r][c4 + 3] = tf32c(pa.w);
        Bs[buf][r][c4 + 0] = tf32c(pb.x); Bs[buf][r][c4 + 1] = tf32c(pb.y);
        Bs[buf][r][c4 + 2] = tf32c(pb.z); Bs[buf][r][c4 + 3] = tf32c(pb.w);
    };

    const int NSTEP = DIM / BK;  // 48
    load_regs(0);
    store_smem(0);

    for (int s = 0; s < NSTEP; s++) {
        __syncthreads();  // buf (s&1) ready; everyone done with step s-1
        const int buf = s & 1;
        if (s + 1 < NSTEP) load_regs((s + 1) * BK);
#pragma unroll
        for (int kk = 0; kk < BK; kk += 8) {
            wmma::fragment<wmma::matrix_a, 16, 16, 8, wmma::precision::tf32, wmma::row_major> af;
            wmma::fragment<wmma::matrix_b, 16, 16, 8, wmma::precision::tf32, wmma::col_major> bf[2];
            wmma::load_matrix_sync(af, &As[buf][warp_m * 16][kk], BK);
#pragma unroll
            for (int j = 0; j < 2; j++)
                wmma::load_matrix_sync(bf[j], &Bs[buf][warp_n * 32 + j * 16][kk], BK);
#pragma unroll
            for (int j = 0; j < 2; j++)
                wmma::mma_sync(acc[j], af, bf[j], acc[j]);
        }
        if (s + 1 < NSTEP) store_smem((s + 1) & 1);
    }
#pragma unroll
    for (int j = 0; j < 2; j++)
        wmma::store_matrix_sync(
            &C[(m0 + warp_m * 16) * DIM + n0 + warp_n * 32 + j * 16],
            acc[j], DIM, wmma::mem_row_major);
}

__global__ void gemm_qkv_kernel(const float* __restrict__ x,
                                const float* __restrict__ Wq,
                                const float* __restrict__ Wk,
                                const float* __restrict__ Wv) {
    const int z = blockIdx.z;
    const float* B = (z == 0) ? Wq : (z == 1) ? Wk : Wv;
    gemm_tile_tf32(x, B, &g_qkv[z][0]);
}

__global__ void gemm_out_kernel(const float* __restrict__ Wp,
                                float* __restrict__ out) {
    gemm_tile_tf32(g_att, Wp, out);
}

// ---------------------------------------------------------------------------
// Epilogue: v = (1-l)*v + l*vi ; q,k = rope(rmsnorm(q|k)); relayout to [h][t][64]
// One warp per (t, head). fp32 exp2f for inv_freq (no FP64 pipe).
// ---------------------------------------------------------------------------
__global__ void qkv_epilogue_kernel(const float* __restrict__ vi,
                                    const float* __restrict__ lamb) {
    const int w = (blockIdx.x * blockDim.x + threadIdx.x) >> 5;
    const int lane = threadIdx.x & 31;
    if (w >= T * NH) return;
    const int t = w / NH;
    const int h = w % NH;

    const int src = t * DIM + h * HD;
    const int dst = (h * T + t) * HD;

    const float invf = exp2f(-13.287712379549449f * (float)lane * (1.0f / 32.0f));
    const float ang = (float)t * invf;
    float sa, ca;
    sincosf(ang, &sa, &ca);

    const float eps = 1.1920929e-07f;

    {
        float a = g_qkv[0][src + lane];
        float b = g_qkv[0][src + 32 + lane];
        float ss = a * a + b * b;
#pragma unroll
        for (int m = 16; m >= 1; m >>= 1) ss += __shfl_xor_sync(0xffffffffu, ss, m);
        float r = rsqrtf(ss * (1.0f / 64.0f) + eps);
        a *= r; b *= r;
        g_q[dst + lane]      = a * ca + b * sa;
        g_q[dst + 32 + lane] = -a * sa + b * ca;
    }
    {
        float a = g_qkv[1][src + lane];
        float b = g_qkv[1][src + 32 + lane];
        float ss = a * a + b * b;
#pragma unroll
        for (int m = 16; m >= 1; m >>= 1) ss += __shfl_xor_sync(0xffffffffu, ss, m);
        float r = rsqrtf(ss * (1.0f / 64.0f) + eps);
        a *= r; b *= r;
        g_k[dst + lane]      = a * ca + b * sa;
        g_k[dst + 32 + lane] = -a * sa + b * ca;
    }
    {
        const float l = lamb[0];
        float va = g_qkv[2][src + lane];
        float vb = g_qkv[2][src + 32 + lane];
        float ia = vi[src + lane];
        float ib = vi[src + 32 + lane];
        g_v[dst + lane]      = (1.0f - l) * va + l * ia;
        g_v[dst + 32 + lane] = (1.0f - l) * vb + l * ib;
    }
}

// ---------------------------------------------------------------------------
// Split-K flash attention, causal, TF32, FIXED-MAX softmax, QT=128.
// 32x32 warp tiles: 4 MMAs per 4 fragment loads (vs 2 per 3 at 16x32) ->
// ~1.8x less smem operand traffic per FLOP (smem BW is the measured
// bottleneck). Split-K over blockIdx.z (chunks of 8 kt-tiles) removes the
// makespan problem that killed plain QT=128 in R7: every CTA runs <=8
// iterations. Partial O (unnormalized) + partial l written per chunk;
// attn_reduce sums and normalizes. 96KB smem -> 2 CTAs/SM.
// ---------------------------------------------------------------------------
__global__ __launch_bounds__(256, 2) void attn_kernel() {
    const int qt = blockIdx.x;
    const int h = blockIdx.y;
    const int c = blockIdx.z;
    const int kt_last = 2 * qt + 1;            // last kt tile for this q-tile
    if (CHUNK_KT * c > kt_last) return;        // chunk beyond causal range

    extern __shared__ float sm[];
    float* Qs = sm;                 // 128x64 (tf32)
    float* Ks = Qs + QT * HD;       // 64x64 (tf32)
    float* Vs = Ks + 64 * HD;       // 64x64 (tf32)
    float* Ss = Vs + 64 * HD;       // 128x64 scores -> P (tf32), then O
    __shared__ float lrow[QT];

    const int tid = threadIdx.x;
    const int wid = tid >> 5;
    const int warp_m = wid >> 1;    // 0..3 -> rows 32*warp_m
    const int warp_n = wid & 1;     // 0..1 -> cols 32*warp_n
    const int q0 = qt * QT;

    const float* qh = g_q + h * T * HD;
    const float* kh = g_k + h * T * HD;
    const float* vh = g_v + h * T * HD;

    // load Q tile (tf32): 128x64
    for (int v = tid; v < QT * 16; v += 256) {
        int r = v >> 4, c4 = (v & 15) * 4;
        float4 q = *(const float4*)&qh[(q0 + r) * HD + c4];
        Qs[r * HD + c4 + 0] = tf32c(q.x);
        Qs[r * HD + c4 + 1] = tf32c(q.y);
        Qs[r * HD + c4 + 2] = tf32c(q.z);
        Qs[r * HD + c4 + 3] = tf32c(q.w);
    }
    if (tid < QT) lrow[tid] = 0.0f;

    // persistent O fragments: 32x32 per warp
    wmma::fragment<wmma::accumulator, 16, 16, 8, float> oacc[2][2];
#pragma unroll
    for (int i = 0; i < 2; i++)
#pragma unroll
        for (int j = 0; j < 2; j++) wmma::fill_fragment(oacc[i][j], 0.0f);

    const int row = tid >> 1;   // 0..127 softmax row
    const int cg = tid & 1;     // col half (32 cols each)

    const int kt0 = CHUNK_KT * c;
    const int kt1 = min(CHUNK_KT * c + CHUNK_KT - 1, kt_last);

    for (int kt = kt0; kt <= kt1; kt++) {
        __syncthreads();  // previous iteration's readers of Ks/Vs/Ss done
        for (int v = tid; v < 64 * 16; v += 256) {
            int r = v >> 4, c4 = (v & 15) * 4;
            float4 k = *(const float4*)&kh[(kt * 64 + r) * HD + c4];
            float4 vv = *(const float4*)&vh[(kt * 64 + r) * HD + c4];
            Ks[r * HD + c4 + 0] = tf32c(k.x);
            Ks[r * HD + c4 + 1] = tf32c(k.y);
            Ks[r * HD + c4 + 2] = tf32c(k.z);
            Ks[r * HD + c4 + 3] = tf32c(k.w);
            Vs[r * HD + c4 + 0] = tf32c(vv.x);
            Vs[r * HD + c4 + 1] = tf32c(vv.y);
            Vs[r * HD + c4 + 2] = tf32c(vv.z);
            Vs[r * HD + c4 + 3] = tf32c(vv.w);
        }
        __syncthreads();

        // S = Q . K^T  (warp: 32 rows x 32 cols)
        {
            wmma::fragment<wmma::accumulator, 16, 16, 8, float> sacc[2][2];
#pragma unroll
            for (int i = 0; i < 2; i++)
#pragma unroll
                for (int j = 0; j < 2; j++) wmma::fill_fragment(sacc[i][j], 0.0f);
#pragma unroll
            for (int kk = 0; kk < HD; kk += 8) {
                wmma::fragment<wmma::matrix_a, 16, 16, 8, wmma::precision::tf32, wmma::row_major> af[2];
                wmma::fragment<wmma::matrix_b, 16, 16, 8, wmma::precision::tf32, wmma::col_major> bf[2];
#pragma unroll
                for (int i = 0; i < 2; i++)
                    wmma::load_matrix_sync(af[i], &Qs[(warp_m * 32 + i * 16) * HD + kk], HD);
#pragma unroll
                for (int j = 0; j < 2; j++)
                    wmma::load_matrix_sync(bf[j], &Ks[(warp_n * 32 + j * 16) * HD + kk], HD);
#pragma unroll
                for (int i = 0; i < 2; i++)
#pragma unroll
                    for (int j = 0; j < 2; j++)
                        wmma::mma_sync(sacc[i][j], af[i], bf[j], sacc[i][j]);
            }
#pragma unroll
            for (int i = 0; i < 2; i++)
#pragma unroll
                for (int j = 0; j < 2; j++)
                    wmma::store_matrix_sync(
                        &Ss[(warp_m * 32 + i * 16) * HD + warp_n * 32 + j * 16],
                        sacc[i][j], HD, wmma::mem_row_major);
        }
        __syncthreads();

        // P = exp(S*scale) with causal mask; accumulate row sums
        {
            const int grow = q0 + row;
            const int gcol0 = kt * 64;
            float rs = 0.0f;
#pragma unroll
            for (int cc0 = 0; cc0 < 32; cc0++) {
                int cc = cg * 32 + cc0;
                float p = (gcol0 + cc > grow)
                              ? 0.0f
                              : __expf(Ss[row * HD + cc] * 0.125f);
                rs += p;
                Ss[row * HD + cc] = tf32c(p);
            }
            rs += __shfl_xor_sync(0xffffffffu, rs, 1);
            if (cg == 0) lrow[row] += rs;
        }
        __syncthreads();

        // O += P . V
#pragma unroll
        for (int kk = 0; kk < 64; kk += 8) {
            wmma::fragment<wmma::matrix_a, 16, 16, 8, wmma::precision::tf32, wmma::row_major> af[2];
            wmma::fragment<wmma::matrix_b, 16, 16, 8, wmma::precision::tf32, wmma::row_major> bf[2];
#pragma unroll
            for (int i = 0; i < 2; i++)
                wmma::load_matrix_sync(af[i], &Ss[(warp_m * 32 + i * 16) * HD + kk], HD);
#pragma unroll
            for (int j = 0; j < 2; j++)
                wmma::load_matrix_sync(bf[j], &Vs[kk * HD + warp_n * 32 + j * 16], HD);
#pragma unroll
            for (int i = 0; i < 2; i++)
#pragma unroll
                for (int j = 0; j < 2; j++)
                    wmma::mma_sync(oacc[i][j], af[i], bf[j], oacc[i][j]);
        }
    }

    // dump partial O (unnormalized) + partial l for this chunk
    __syncthreads();
#pragma unroll
    for (int i = 0; i < 2; i++)
#pragma unroll
        for (int j = 0; j < 2; j++)
            wmma::store_matrix_sync(
                &Ss[(warp_m * 32 + i * 16) * HD + warp_n * 32 + j * 16],
                oacc[i][j], HD, wmma::mem_row_major);
    __syncthreads();
#pragma unroll
    for (int cc0 = 0; cc0 < 8; cc0++) {
        int cc = cg * 32 + cc0 * 4;
        *(float4*)&g_opart[c][(q0 + row) * DIM + h * HD + cc] =
            *(const float4*)&Ss[row * HD + cc];
    }
    if (tid < QT) g_lpart[c][h * T + q0 + tid] = lrow[tid];
}

// ---------------------------------------------------------------------------
// Reduce: sum active chunks' partial O / l per row, normalize -> g_att.
// qt = t/128; last kt tile = 2qt+1; nch = (2qt+1)/8 + 1.
// ---------------------------------------------------------------------------
__global__ void attn_reduce_kernel() {
    const int idx = blockIdx.x * blockDim.x + threadIdx.x;  // over T*DIM/4
    const int t = idx / (DIM / 4);
    const int d = (idx % (DIM / 4)) * 4;
    const int h = d / HD;
    const int qt = t >> 7;
    const int nch = ((2 * qt + 1) >> 3) + 1;

    float4 o = make_float4(0.f, 0.f, 0.f, 0.f);
    float l = 0.f;
    for (int c = 0; c < nch; c++) {
        float4 p = *(const float4*)&g_opart[c][t * DIM + d];
        o.x += p.x; o.y += p.y; o.z += p.z; o.w += p.w;
        l += g_lpart[c][h * T + t];
    }
    float inv = 1.0f / l;
    o.x *= inv; o.y *= inv; o.z *= inv; o.w *= inv;
    *(float4*)&g_att[t * DIM + d] = o;
}

// ---------------------------------------------------------------------------
extern "C" void kernel_launch(void* const* d_in, const int* in_sizes, int n_in,
                              void* d_out, int out_size) {
    const float* x    = (const float*)d_in[0];
    const float* vi   = (const float*)d_in[1];
    const float* Wq   = (const float*)d_in[2];
    const float* Wk   = (const float*)d_in[3];
    const float* Wv   = (const float*)d_in[4];
    const float* Wp   = (const float*)d_in[5];
    const float* lamb = (const float*)d_in[6];
    float* out = (float*)d_out;

    const int attn_smem = (QT * HD + 64 * HD + 64 * HD + QT * HD) * sizeof(float);  // 96KB

    static bool attr_set = false;
    if (!attr_set) {
        cudaFuncSetAttribute(attn_kernel,
                             cudaFuncAttributeMaxDynamicSharedMemorySize,
                             attn_smem);
        attr_set = true;
    }

    dim3 gqkv(DIM / BN, T / BM, 3);
    gemm_qkv_kernel<<<gqkv, 256>>>(x, Wq, Wk, Wv);

    qkv_epilogue_kernel<<<(T * NH * 32) / 256, 256>>>(vi, lamb);

    dim3 gattn(T / QT, NH, NCHUNK);
    attn_kernel<<<gattn, 256, attn_smem>>>();

    attn_reduce_kernel<<<(T * DIM / 4) / 256, 256>>>();

    dim3 gout(DIM / BN, T / BM, 1);
    gemm_out_kernel<<<gout, 256>>>(Wp, out);
}

// round 16
// speedup vs baseline: 1.2759x; 1.2759x over previous
#include <cuda_runtime.h>
#include <mma.h>
#include <math.h>

using namespace nvcuda;

#define T 2048
#define DIM 768
#define NH 12
#define HD 64
#define NCHUNK 4          // kt chunks per q-tile (8 kt-tiles = 512 keys each)
#define CHUNK_KT 8

// Scratch (allocation-free: __device__ globals)
__device__ float g_qkv[3][T * DIM];        // raw q,k,v projections, [t][768]
__device__ float g_q[T * DIM];             // [h][t][64]
__device__ float g_k[T * DIM];             // [h][t][64]
__device__ float g_v[T * DIM];             // [h][t][64]
__device__ float g_att[T * DIM];           // attention output, [t][768]
__device__ float g_opart[NCHUNK][T * DIM]; // unnormalized partial O per chunk
__device__ float g_lpart[NCHUNK][NH * T];  // partial row sums per chunk

__device__ __forceinline__ float tf32c(float x) { return wmma::__float_to_tf32(x); }

// ---------------------------------------------------------------------------
// TF32 wmma GEMM-NT: C[m][n] = sum_k A[m*DIM+k] * B[n*DIM+k]
// Same proven per-warp pattern as the 84.9us kernel (32x32 warp tile, BK=16,
// two-sync single-buffer), but CTA shrunk to 4 warps / 64x64 so the grid is
// 2x bigger (384 / 1152 CTAs) and 4+ CTAs co-reside per SM to hide the
// barrier + fragment-load latency that capped occ at 16%.
// ---------------------------------------------------------------------------
#define BM 64
#define BN 64
#define BK 16

__device__ __forceinline__ void gemm_tile_tf32(const float* __restrict__ A,
                                               const float* __restrict__ B,
                                               float* __restrict__ C) {
    __shared__ float As[BM][BK];   // [m][k]
    __shared__ float Bs[BN][BK];   // [n][k]
    const int tid = threadIdx.x;   // 0..127
    const int wid = tid >> 5;      // 0..3
    const int m0 = blockIdx.y * BM, n0 = blockIdx.x * BN;
    const int warp_m = wid >> 1;   // 0..1 -> 32-row slice
    const int warp_n = wid & 1;    // 0..1 -> 32-col slice

    wmma::fragment<wmma::accumulator, 16, 16, 8, float> acc[2][2];
#pragma unroll
    for (int i = 0; i < 2; i++)
#pragma unroll
        for (int j = 0; j < 2; j++) wmma::fill_fragment(acc[i][j], 0.0f);

    for (int k0 = 0; k0 < DIM; k0 += BK) {
        __syncthreads();
#pragma unroll
        for (int v = tid; v < BM * BK / 4; v += 128) {
            int r = v >> 2, c4 = (v & 3) * 4;
            float4 a = *(const float4*)&A[(m0 + r) * DIM + k0 + c4];
            As[r][c4 + 0] = tf32c(a.x);
            As[r][c4 + 1] = tf32c(a.y);
            As[r][c4 + 2] = tf32c(a.z);
            As[r][c4 + 3] = tf32c(a.w);
        }
#pragma unroll
        for (int v = tid; v < BN * BK / 4; v += 128) {
            int r = v >> 2, c4 = (v & 3) * 4;
            float4 b = *(const float4*)&B[(n0 + r) * DIM + k0 + c4];
            Bs[r][c4 + 0] = tf32c(b.x);
            Bs[r][c4 + 1] = tf32c(b.y);
            Bs[r][c4 + 2] = tf32c(b.z);
            Bs[r][c4 + 3] = tf32c(b.w);
        }
        __syncthreads();
#pragma unroll
        for (int kk = 0; kk < BK; kk += 8) {
            wmma::fragment<wmma::matrix_a, 16, 16, 8, wmma::precision::tf32, wmma::row_major> af[2];
            wmma::fragment<wmma::matrix_b, 16, 16, 8, wmma::precision::tf32, wmma::col_major> bf[2];
#pragma unroll
            for (int i = 0; i < 2; i++)
                wmma::load_matrix_sync(af[i], &As[warp_m * 32 + i * 16][kk], BK);
#pragma unroll
            for (int j = 0; j < 2; j++)
                wmma::load_matrix_sync(bf[j], &Bs[warp_n * 32 + j * 16][kk], BK);
#pragma unroll
            for (int i = 0; i < 2; i++)
#pragma unroll
                for (int j = 0; j < 2; j++)
                    wmma::mma_sync(acc[i][j], af[i], bf[j], acc[i][j]);
        }
    }
#pragma unroll
    for (int i = 0; i < 2; i++)
#pragma unroll
        for (int j = 0; j < 2; j++)
            wmma::store_matrix_sync(
                &C[(m0 + warp_m * 32 + i * 16) * DIM + n0 + warp_n * 32 + j * 16],
                acc[i][j], DIM, wmma::mem_row_major);
}

__global__ void gemm_qkv_kernel(const float* __restrict__ x,
                                const float* __restrict__ Wq,
                                const float* __restrict__ Wk,
                                const float* __restrict__ Wv) {
    const int z = blockIdx.z;
    const float* B = (z == 0) ? Wq : (z == 1) ? Wk : Wv;
    gemm_tile_tf32(x, B, &g_qkv[z][0]);
}

__global__ void gemm_out_kernel(const float* __restrict__ Wp,
                                float* __restrict__ out) {
    gemm_tile_tf32(g_att, Wp, out);
}

// ---------------------------------------------------------------------------
// Epilogue: v = (1-l)*v + l*vi ; q,k = rope(rmsnorm(q|k)); relayout to [h][t][64]
// One warp per (t, head). fp32 exp2f for inv_freq (no FP64 pipe).
// ---------------------------------------------------------------------------
__global__ void qkv_epilogue_kernel(const float* __restrict__ vi,
                                    const float* __restrict__ lamb) {
    const int w = (blockIdx.x * blockDim.x + threadIdx.x) >> 5;
    const int lane = threadIdx.x & 31;
    if (w >= T * NH) return;
    const int t = w / NH;
    const int h = w % NH;

    const int src = t * DIM + h * HD;
    const int dst = (h * T + t) * HD;

    const float invf = exp2f(-13.287712379549449f * (float)lane * (1.0f / 32.0f));
    const float ang = (float)t * invf;
    float sa, ca;
    sincosf(ang, &sa, &ca);

    const float eps = 1.1920929e-07f;

    {
        float a = g_qkv[0][src + lane];
        float b = g_qkv[0][src + 32 + lane];
        float ss = a * a + b * b;
#pragma unroll
        for (int m = 16; m >= 1; m >>= 1) ss += __shfl_xor_sync(0xffffffffu, ss, m);
        float r = rsqrtf(ss * (1.0f / 64.0f) + eps);
        a *= r; b *= r;
        g_q[dst + lane]      = a * ca + b * sa;
        g_q[dst + 32 + lane] = -a * sa + b * ca;
    }
    {
        float a = g_qkv[1][src + lane];
        float b = g_qkv[1][src + 32 + lane];
        float ss = a * a + b * b;
#pragma unroll
        for (int m = 16; m >= 1; m >>= 1) ss += __shfl_xor_sync(0xffffffffu, ss, m);
        float r = rsqrtf(ss * (1.0f / 64.0f) + eps);
        a *= r; b *= r;
        g_k[dst + lane]      = a * ca + b * sa;
        g_k[dst + 32 + lane] = -a * sa + b * ca;
    }
    {
        const float l = lamb[0];
        float va = g_qkv[2][src + lane];
        float vb = g_qkv[2][src + 32 + lane];
        float ia = vi[src + lane];
        float ib = vi[src + 32 + lane];
        g_v[dst + lane]      = (1.0f - l) * va + l * ia;
        g_v[dst + 32 + lane] = (1.0f - l) * vb + l * ib;
    }
}

// ---------------------------------------------------------------------------
// Split-K flash attention (R11 measured-good), causal, TF32, FIXED-MAX
// softmax (valid: rms_norm gives |q|=|k|=8 -> scores in [-8,8], no overflow).
// Attention is a pure sum over kt, split into chunks of 8 kt-tiles across
// blockIdx.z; partial O (unnormalized) + partial l written per chunk;
// attn_reduce sums <=4 partials and normalizes.
// ---------------------------------------------------------------------------
__global__ void attn_kernel() {
    const int qt = blockIdx.x;
    const int h = blockIdx.y;
    const int c = blockIdx.z;
    if (CHUNK_KT * c > qt) return;  // chunk beyond causal range

    extern __shared__ float sm[];
    float* Qs = sm;              // 64x64 (tf32)
    float* Ks = Qs + 4096;       // 64x64 (tf32)
    float* Vs = Ks + 4096;       // 64x64 (tf32)
    float* Ss = Vs + 4096;       // 64x64 scores -> P (tf32), then O at the end
    __shared__ float lrow[64];

    const int tid = threadIdx.x;
    const int wid = tid >> 5;
    const int warp_m = wid >> 1;  // 0..3
    const int warp_n = wid & 1;   // 0..1
    const int q0 = qt * 64;

    const float* qh = g_q + h * T * HD;
    const float* kh = g_k + h * T * HD;
    const float* vh = g_v + h * T * HD;

    // load Q tile (tf32)
    for (int v = tid; v < 64 * 16; v += 256) {
        int r = v >> 4, c4 = (v & 15) * 4;
        float4 q = *(const float4*)&qh[(q0 + r) * HD + c4];
        Qs[r * 64 + c4 + 0] = tf32c(q.x);
        Qs[r * 64 + c4 + 1] = tf32c(q.y);
        Qs[r * 64 + c4 + 2] = tf32c(q.z);
        Qs[r * 64 + c4 + 3] = tf32c(q.w);
    }
    if (tid < 64) lrow[tid] = 0.0f;

    wmma::fragment<wmma::accumulator, 16, 16, 8, float> oacc[2];
#pragma unroll
    for (int j = 0; j < 2; j++) wmma::fill_fragment(oacc[j], 0.0f);

    const int row = tid >> 2;     // 0..63 softmax row
    const int cg = tid & 3;       // col group, 16 cols each

    const int kt0 = CHUNK_KT * c;
    const int kt1 = min(CHUNK_KT * c + CHUNK_KT - 1, qt);

    for (int kt = kt0; kt <= kt1; kt++) {
        __syncthreads();  // previous iter's PV readers of Ks/Vs/Ss done
        for (int v = tid; v < 64 * 16; v += 256) {
            int r = v >> 4, c4 = (v & 15) * 4;
            float4 k = *(const float4*)&kh[(kt * 64 + r) * HD + c4];
            float4 vv = *(const float4*)&vh[(kt * 64 + r) * HD + c4];
            Ks[r * 64 + c4 + 0] = tf32c(k.x);
            Ks[r * 64 + c4 + 1] = tf32c(k.y);
            Ks[r * 64 + c4 + 2] = tf32c(k.z);
            Ks[r * 64 + c4 + 3] = tf32c(k.w);
            Vs[r * 64 + c4 + 0] = tf32c(vv.x);
            Vs[r * 64 + c4 + 1] = tf32c(vv.y);
            Vs[r * 64 + c4 + 2] = tf32c(vv.z);
            Vs[r * 64 + c4 + 3] = tf32c(vv.w);
        }
        __syncthreads();

        // S = Q . K^T
        {
            wmma::fragment<wmma::accumulator, 16, 16, 8, float> sacc[2];
#pragma unroll
            for (int j = 0; j < 2; j++) wmma::fill_fragment(sacc[j], 0.0f);
#pragma unroll
            for (int kk = 0; kk < 64; kk += 8) {
                wmma::fragment<wmma::matrix_a, 16, 16, 8, wmma::precision::tf32, wmma::row_major> af;
                wmma::fragment<wmma::matrix_b, 16, 16, 8, wmma::precision::tf32, wmma::col_major> bf[2];
                wmma::load_matrix_sync(af, &Qs[(warp_m * 16) * 64 + kk], 64);
#pragma unroll
                for (int j = 0; j < 2; j++)
                    wmma::load_matrix_sync(bf[j], &Ks[(warp_n * 32 + j * 16) * 64 + kk], 64);
#pragma unroll
                for (int j = 0; j < 2; j++)
                    wmma::mma_sync(sacc[j], af, bf[j], sacc[j]);
            }
#pragma unroll
            for (int j = 0; j < 2; j++)
                wmma::store_matrix_sync(&Ss[(warp_m * 16) * 64 + warp_n * 32 + j * 16],
                                        sacc[j], 64, wmma::mem_row_major);
        }
        __syncthreads();

        // P = exp(S*scale) with causal mask on diagonal tile; row sums
        {
            const bool diag = (kt == qt);
            float rs = 0.0f;
#pragma unroll
            for (int cc0 = 0; cc0 < 16; cc0++) {
                int cc = cg * 16 + cc0;
                float p;
                if (diag && cc > row) {
                    p = 0.0f;
                } else {
                    p = __expf(Ss[row * 64 + cc] * 0.125f);
                }
                rs += p;
                Ss[row * 64 + cc] = tf32c(p);
            }
            rs += __shfl_xor_sync(0xffffffffu, rs, 1);
            rs += __shfl_xor_sync(0xffffffffu, rs, 2);
            if (cg == 0) lrow[row] += rs;
        }
        __syncthreads();

        // O += P . V
#pragma unroll
        for (int kk = 0; kk < 64; kk += 8) {
            wmma::fragment<wmma::matrix_a, 16, 16, 8, wmma::precision::tf32, wmma::row_major> af;
            wmma::fragment<wmma::matrix_b, 16, 16, 8, wmma::precision::tf32, wmma::row_major> bf[2];
            wmma::load_matrix_sync(af, &Ss[(warp_m * 16) * 64 + kk], 64);
#pragma unroll
            for (int j = 0; j < 2; j++)
                wmma::load_matrix_sync(bf[j], &Vs[kk * 64 + warp_n * 32 + j * 16], 64);
#pragma unroll
            for (int j = 0; j < 2; j++)
                wmma::mma_sync(oacc[j], af, bf[j], oacc[j]);
        }
    }

    // dump partial O (unnormalized) + partial l for this chunk
    __syncthreads();
#pragma unroll
    for (int j = 0; j < 2; j++)
        wmma::store_matrix_sync(&Ss[(warp_m * 16) * 64 + warp_n * 32 + j * 16],
                                oacc[j], 64, wmma::mem_row_major);
    __syncthreads();
#pragma unroll
    for (int cc0 = 0; cc0 < 4; cc0++) {
        int cc = cg * 16 + cc0 * 4;
        *(float4*)&g_opart[c][(q0 + row) * DIM + h * HD + cc] =
            *(const float4*)&Ss[row * 64 + cc];
    }
    if (tid < 64) g_lpart[c][h * T + q0 + tid] = lrow[tid];
}

// ---------------------------------------------------------------------------
// Reduce: sum the active chunks' partial O / l per row, normalize -> g_att.
// Chunks beyond the causal range were never written; nch(qt) = qt/8 + 1.
// ---------------------------------------------------------------------------
__global__ void attn_reduce_kernel() {
    const int idx = blockIdx.x * blockDim.x + threadIdx.x;  // over T*DIM/4
    const int t = idx / (DIM / 4);
    const int d = (idx % (DIM / 4)) * 4;
    const int h = d / HD;
    const int nch = (t >> 6 >> 3) + 1;  // qt = t/64, nch = qt/8 + 1

    float4 o = make_float4(0.f, 0.f, 0.f, 0.f);
    float l = 0.f;
    for (int c = 0; c < nch; c++) {
        float4 p = *(const float4*)&g_opart[c][t * DIM + d];
        o.x += p.x; o.y += p.y; o.z += p.z; o.w += p.w;
        l += g_lpart[c][h * T + t];
    }
    float inv = 1.0f / l;
    o.x *= inv; o.y *= inv; o.z *= inv; o.w *= inv;
    *(float4*)&g_att[t * DIM + d] = o;
}

// ---------------------------------------------------------------------------
extern "C" void kernel_launch(void* const* d_in, const int* in_sizes, int n_in,
                              void* d_out, int out_size) {
    const float* x    = (const float*)d_in[0];
    const float* vi   = (const float*)d_in[1];
    const float* Wq   = (const float*)d_in[2];
    const float* Wk   = (const float*)d_in[3];
    const float* Wv   = (const float*)d_in[4];
    const float* Wp   = (const float*)d_in[5];
    const float* lamb = (const float*)d_in[6];
    float* out = (float*)d_out;

    static bool attr_set = false;
    if (!attr_set) {
        cudaFuncSetAttribute(attn_kernel,
                             cudaFuncAttributeMaxDynamicSharedMemorySize,
                             4 * 4096 * sizeof(float));
        attr_set = true;
    }

    dim3 gqkv(DIM / BN, T / BM, 3);
    gemm_qkv_kernel<<<gqkv, 128>>>(x, Wq, Wk, Wv);

    qkv_epilogue_kernel<<<(T * NH * 32) / 256, 256>>>(vi, lamb);

    dim3 gattn(T / 64, NH, NCHUNK);
    attn_kernel<<<gattn, 256, 4 * 4096 * sizeof(float)>>>();

    attn_reduce_kernel<<<(T * DIM / 4) / 256, 256>>>();

    dim3 gout(DIM / BN, T / BM, 1);
    gemm_out_kernel<<<gout, 128>>>(Wp, out);
}